// round 16
// baseline (speedup 1.0000x reference)
#include <cuda_runtime.h>

// ---------------------------------------------------------------------------
// v10: tap-sorted GEMM, 4 launches.
//   k_prep      : per-tap emb -> W -> dense duplicated 80x80 kernel
//   k_scatter   : vol[voxel] = i+1 (idempotent), reset counters
//   k_probeself : self+center term + MIRROR probing (62 taps -> both
//                 directions), hits straight into per-tap regions
//   k_gemm      : persistent tiles; 16 hits x 4 ch per thread, GT=160,
//                 skewed fsT (conflict-free), B broadcast; f32x2 FMA;
//                 scatter via red.global.add.v4.f32
// ---------------------------------------------------------------------------

#define GRIDL 192
#define NVOX  (192*192*192)
#define NTAP  125
#define CTAP  62
#define NSEQ  124
#define RCAP  8192
#define TM    128
#define GT    160
#define NCTA  296
#define MAXT  50
#define NTK   (NSEQ*MAXT)
#define FST3  160              // fsT/wdup row stride (floats)

__device__ float g_Wc[2304];
__device__ float g_Kdup[(size_t)NSEQ * 12800];
__device__ int   g_vol[NVOX];
__device__ int   g_tcnt[NSEQ];
__device__ int2  g_hits[(size_t)NSEQ * RCAP];

// ---- asm helpers -----------------------------------------------------------
__device__ __forceinline__ void cp16(void* dst, const void* src) {
    unsigned d = (unsigned)__cvta_generic_to_shared(dst);
    asm volatile("cp.async.cg.shared.global [%0], [%1], 16;\n" :: "r"(d), "l"(src));
}
__device__ __forceinline__ void cp_commit() { asm volatile("cp.async.commit_group;\n"); }
__device__ __forceinline__ void cp_wait0() { asm volatile("cp.async.wait_group 0;\n" ::: "memory"); }
__device__ __forceinline__ void ffma2(unsigned long long& d, unsigned long long a,
                                      unsigned long long b) {
    asm volatile("fma.rn.f32x2 %0, %1, %2, %0;" : "+l"(d) : "l"(a), "l"(b));
}
__device__ __forceinline__ void red4(float* p, float a, float b, float c, float d) {
    asm volatile("red.global.add.v4.f32 [%0], {%1,%2,%3,%4};"
                 :: "l"(p), "f"(a), "f"(b), "f"(c), "f"(d) : "memory");
}
__device__ __forceinline__ float lo32(unsigned long long v) {
    return __uint_as_float((unsigned)v);
}
__device__ __forceinline__ float hi32(unsigned long long v) {
    return __uint_as_float((unsigned)(v >> 32));
}

// ---- k_prep ----------------------------------------------------------------
__global__ void k_prep(const float* __restrict__ weight) {
    __shared__ float e[8];
    __shared__ float sW[2304];
    const int p = blockIdx.x;
    const int tid = threadIdx.x;

    float dx = (float)(p / 25) - 2.f;
    float dy = (float)((p / 5) % 5) - 2.f;
    float dz = (float)(p % 5) - 2.f;
    if (tid < 8) {
        float d = sqrtf(dx * dx + dy * dy + dz * dz);
        const float step = 2.5f / 9.f;
        float c = step * (float)(tid + 1);
        float t = (d - c) / step;
        float ev = 0.f;
        if (fabsf(t) < 1.f) {
            float s = 1.f - t * t;
            ev = 1.14136f * expf(2.f) * expf(-2.f / s);
        }
        e[tid] = ev;
    }
    __syncthreads();

    const float ALPHA = 0.14433756729740643f;
    const float INV125 = 1.f / 125.f;
    const float INVS3 = 0.5773502691896258f;
    for (int c = tid; c < 2304; c += blockDim.x) {
        float s = 0.f;
        #pragma unroll
        for (int r = 0; r < 8; r++) s += e[r] * weight[r * 2304 + c];
        s *= INV125;
        float sc = (c < 1792) ? ALPHA : ALPHA * INVS3;
        s *= sc;
        sW[c] = s;
        if (p == CTAP) g_Wc[c] = s;
    }
    __syncthreads();

    if (p == CTAP) return;
    const int seq = p - (p > CTAP);
    float d2 = dx * dx + dy * dy + dz * dz;
    float inv = 1.7320508075688772f / sqrtf(d2);
    float v[3] = {dx * inv, dy * inv, dz * inv};
    float* D = g_Kdup + (size_t)seq * 12800;
    for (int idx = tid; idx < 6400; idx += blockDim.x) {
        int j = idx / 80, c = idx % 80;
        float val;
        if (j < 32) {
            if (c < 32) val = sW[j * 32 + c];
            else { int cc = c - 32; val = sW[1024 + j * 16 + cc / 3] * v[cc % 3]; }
        } else {
            int jj = j - 32; int i = jj / 3, m = jj % 3;
            if (c < 32) val = sW[1792 + i * 32 + c] * v[m];
            else { int cc = c - 32;
                   val = (m == cc % 3) ? sW[1536 + i * 16 + cc / 3] : 0.f; }
        }
        D[j * 160 + 2 * c] = val;
        D[j * 160 + 2 * c + 1] = val;
    }
}

// ---- k_scatter -------------------------------------------------------------
__global__ void k_scatter(const int* __restrict__ coords, int n) {
    int i = blockIdx.x * blockDim.x + threadIdx.x;
    if (i < NSEQ) g_tcnt[i] = 0;
    if (i < n) {
        int x = coords[3 * i], y = coords[3 * i + 1], z = coords[3 * i + 2];
        g_vol[(x * GRIDL + y) * GRIDL + z] = i + 1;
    }
}

// ---- k_probeself: self+center + mirror probing -----------------------------
__global__ void k_probeself(const float* __restrict__ feats,
                            const float* __restrict__ wsc0,
                            const float* __restrict__ wsc1,
                            const int* __restrict__ coords,
                            float* __restrict__ out, int n)
{
    __shared__ float w0s[1024];
    __shared__ float w1s[256];
    __shared__ int bcnt[NSEQ];
    __shared__ int gbase[NSEQ];
    const int tid = threadIdx.x;

    if (tid < NSEQ) bcnt[tid] = 0;
    for (int i = tid; i < 1024; i += 256)
        w0s[i] = wsc0[i] * 0.17677669529663687f + g_Wc[i];
    if (tid < 256)
        w1s[tid] = wsc1[tid] * 0.25f + g_Wc[1536 + tid];
    __syncthreads();

    const int pt = blockIdx.x * 256 + tid;
    const bool valid = (pt < n);
    int cx = 0, cy = 0, cz = 0;
    unsigned m[2] = {0u, 0u};    // 62 probe taps (p = 0..61)

    if (valid) {
        cx = coords[3 * pt]; cy = coords[3 * pt + 1]; cz = coords[3 * pt + 2];

        // self + center term
        const float* f = feats + (size_t)pt * 80;
        float* o = out + (size_t)pt * 80;
        float fr[48];
        #pragma unroll
        for (int i = 0; i < 32; i++) fr[i] = f[i];
        #pragma unroll
        for (int c = 0; c < 32; c++) {
            float s = 0.f;
            #pragma unroll
            for (int i = 0; i < 32; i++) s += fr[i] * w0s[i * 32 + c];
            o[c] = s;
        }
        #pragma unroll
        for (int i = 0; i < 48; i++) fr[i] = f[32 + i];
        #pragma unroll
        for (int k = 0; k < 16; k++) {
            float s0 = 0.f, s1 = 0.f, s2 = 0.f;
            #pragma unroll
            for (int i = 0; i < 16; i++) {
                float w = w1s[i * 16 + k];
                s0 += fr[i * 3 + 0] * w;
                s1 += fr[i * 3 + 1] * w;
                s2 += fr[i * 3 + 2] * w;
            }
            o[32 + k * 3 + 0] = s0;
            o[32 + k * 3 + 1] = s1;
            o[32 + k * 3 + 2] = s2;
        }

        // pass A: probe taps 0..61; hit => both directions exist
        #pragma unroll
        for (int w = 0; w < 2; w++) {
            unsigned mw = 0u;
            #pragma unroll 4
            for (int j = 0; j < 32; j++) {
                int p = w * 32 + j;
                if (p < CTAP) {
                    int x = cx + p / 25 - 2, y = cy + (p / 5) % 5 - 2, z = cz + p % 5 - 2;
                    if ((unsigned)x < (unsigned)GRIDL && (unsigned)y < (unsigned)GRIDL &&
                        (unsigned)z < (unsigned)GRIDL) {
                        if (__ldg(&g_vol[(x * GRIDL + y) * GRIDL + z]) > 0) {
                            mw |= (1u << j);
                            atomicAdd(&bcnt[p], 1);          // seq(p) = p (p<62)
                            atomicAdd(&bcnt[123 - p], 1);    // seq(124-p)
                        }
                    }
                }
            }
            m[w] = mw;
        }
    }
    __syncthreads();

    if (tid < NSEQ) {
        int c = bcnt[tid];
        gbase[tid] = c ? (tid * RCAP + atomicAdd(&g_tcnt[tid], c)) : 0;
        bcnt[tid] = 0;
    }
    __syncthreads();

    // pass B: re-probe hits; write forward + mirrored records
    if (valid) {
        #pragma unroll
        for (int w = 0; w < 2; w++) {
            unsigned mw = m[w];
            while (mw) {
                int j = __ffs(mw) - 1; mw &= mw - 1;
                int p = w * 32 + j;
                int x = cx + p / 25 - 2, y = cy + (p / 5) % 5 - 2, z = cz + p % 5 - 2;
                int nb = g_vol[(x * GRIDL + y) * GRIDL + z] - 1;
                int sf = p, sb = 123 - p;
                int slotf = gbase[sf] + atomicAdd(&bcnt[sf], 1);
                if (slotf < (sf + 1) * RCAP) g_hits[slotf] = make_int2(nb, pt);
                int slotb = gbase[sb] + atomicAdd(&bcnt[sb], 1);
                if (slotb < (sb + 1) * RCAP) g_hits[slotb] = make_int2(pt, nb);
            }
        }
    }
}

// ---- k_gemm: 16 hits x 4 ch per thread, GT=160 -----------------------------
__global__ void __launch_bounds__(GT, 2)
k_gemm(const float* __restrict__ feats, float* __restrict__ out)
{
    extern __shared__ float smg[];
    float* fsT  = smg;               // [80][160]: hit-group hg at hg*20 (skew)
    float* wdup = smg + 80 * FST3;   // [80][160]

    const int tid = threadIdx.x;
    const int wp = tid >> 5, lane = tid & 31;
    const int hg = lane & 7;                  // 8 hit groups x 16 hits
    const int cgq = wp * 4 + (lane >> 3);     // 0..19, 4 channels each
    const int hb = hg * 16;
    const int aoff = hg * 20;

    const int t0 = (int)((long long)blockIdx.x * NTK / NCTA);
    const int t1 = (int)((long long)(blockIdx.x + 1) * NTK / NCTA);
    int cur_seq = -1;

    for (int t = t0; t < t1; t++) {
        const int seq = t / MAXT, lt = t - seq * MAXT;
        int cnt = g_tcnt[seq];
        if (cnt > MAXT * TM) cnt = MAXT * TM;
        if (lt * TM >= cnt) continue;
        const int base = seq * RCAP + lt * TM;
        int cnt_t = cnt - lt * TM;
        if (cnt_t > TM) cnt_t = TM;

        __syncthreads();

        const bool neww = (seq != cur_seq);
        if (neww) {
            cur_seq = seq;
            const float4* ws = (const float4*)(g_Kdup + (size_t)seq * 12800);
            float4* wd = (float4*)wdup;
            #pragma unroll
            for (int k = 0; k < 20; k++) cp16(wd + tid + k * GT, ws + tid + k * GT);
            cp_commit();
        }
        // gather feats -> skewed transpose: hit h -> (h>>4)*20 + (h&15)
        #pragma unroll
        for (int i = 0; i < 16; i++) {
            int idx = tid + i * GT;
            int kq = idx >> 7, h = idx & 127;
            int hh = (h < cnt_t) ? h : cnt_t - 1;
            int src = g_hits[base + hh].x;
            float4 f = __ldg((const float4*)(feats + (size_t)src * 80) + kq);
            int foff = (h >> 4) * 20 + (h & 15);
            int kb = kq * 4;
            fsT[(kb + 0) * FST3 + foff] = f.x;
            fsT[(kb + 1) * FST3 + foff] = f.y;
            fsT[(kb + 2) * FST3 + foff] = f.z;
            fsT[(kb + 3) * FST3 + foff] = f.w;
        }
        if (neww) cp_wait0();
        __syncthreads();

        unsigned long long acc[8][4];
        #pragma unroll
        for (int a = 0; a < 8; a++)
            #pragma unroll
            for (int b = 0; b < 4; b++) acc[a][b] = 0ull;

        #pragma unroll 2
        for (int k = 0; k < 80; k++) {
            const ulonglong2* fa = (const ulonglong2*)(fsT + k * FST3 + aoff);
            ulonglong2 A0 = fa[0], A1 = fa[1], A2 = fa[2], A3 = fa[3];
            const ulonglong2* wb = (const ulonglong2*)(wdup + k * FST3 + cgq * 8);
            ulonglong2 B0 = wb[0], B1 = wb[1];
            ffma2(acc[0][0], A0.x, B0.x); ffma2(acc[0][1], A0.x, B0.y);
            ffma2(acc[0][2], A0.x, B1.x); ffma2(acc[0][3], A0.x, B1.y);
            ffma2(acc[1][0], A0.y, B0.x); ffma2(acc[1][1], A0.y, B0.y);
            ffma2(acc[1][2], A0.y, B1.x); ffma2(acc[1][3], A0.y, B1.y);
            ffma2(acc[2][0], A1.x, B0.x); ffma2(acc[2][1], A1.x, B0.y);
            ffma2(acc[2][2], A1.x, B1.x); ffma2(acc[2][3], A1.x, B1.y);
            ffma2(acc[3][0], A1.y, B0.x); ffma2(acc[3][1], A1.y, B0.y);
            ffma2(acc[3][2], A1.y, B1.x); ffma2(acc[3][3], A1.y, B1.y);
            ffma2(acc[4][0], A2.x, B0.x); ffma2(acc[4][1], A2.x, B0.y);
            ffma2(acc[4][2], A2.x, B1.x); ffma2(acc[4][3], A2.x, B1.y);
            ffma2(acc[5][0], A2.y, B0.x); ffma2(acc[5][1], A2.y, B0.y);
            ffma2(acc[5][2], A2.y, B1.x); ffma2(acc[5][3], A2.y, B1.y);
            ffma2(acc[6][0], A3.x, B0.x); ffma2(acc[6][1], A3.x, B0.y);
            ffma2(acc[6][2], A3.x, B1.x); ffma2(acc[6][3], A3.x, B1.y);
            ffma2(acc[7][0], A3.y, B0.x); ffma2(acc[7][1], A3.y, B0.y);
            ffma2(acc[7][2], A3.y, B1.x); ffma2(acc[7][3], A3.y, B1.y);
        }

        #pragma unroll
        for (int pr = 0; pr < 8; pr++) {
            int h0 = hb + pr * 2;
            if (h0 < cnt_t) {
                int dst = g_hits[base + h0].y;
                red4(out + (size_t)dst * 80 + cgq * 4,
                     lo32(acc[pr][0]), lo32(acc[pr][1]),
                     lo32(acc[pr][2]), lo32(acc[pr][3]));
            }
            if (h0 + 1 < cnt_t) {
                int dst = g_hits[base + h0 + 1].y;
                red4(out + (size_t)dst * 80 + cgq * 4,
                     hi32(acc[pr][0]), hi32(acc[pr][1]),
                     hi32(acc[pr][2]), hi32(acc[pr][3]));
            }
        }
    }
}

// ---------------------------------------------------------------------------
extern "C" void kernel_launch(void* const* d_in, const int* in_sizes, int n_in,
                              void* d_out, int out_size) {
    const float* feats  = (const float*)d_in[0];
    const float* weight = (const float*)d_in[1];
    const float* wsc0   = (const float*)d_in[2];
    const float* wsc1   = (const float*)d_in[3];
    const int*   coords = (const int*)d_in[4];
    float* out = (float*)d_out;
    int n = in_sizes[0] / 80;

    const int SMG = (80 * FST3 + 80 * FST3) * 4;
    cudaFuncSetAttribute(k_gemm, cudaFuncAttributeMaxDynamicSharedMemorySize, SMG);

    int nblk = (n + 255) / 256;
    k_prep<<<NTAP, 256>>>(weight);
    k_scatter<<<nblk, 256>>>(coords, n);
    k_probeself<<<nblk, 256>>>(feats, wsc0, wsc1, coords, out, n);
    k_gemm<<<NCTA, GT, SMG>>>(feats, out);
}

// round 17
// speedup vs baseline: 1.2367x; 1.2367x over previous
#include <cuda_runtime.h>

// ---------------------------------------------------------------------------
// v11: best measured halves recombined.
//   k_gemm      : exact v9 config (GT=320, 8 hits x 4 ch, skewed fsT,
//                 B-broadcast warp map, f32x2 FMA, red.global.add.v4.f32)
//                 -- measured 331 us
//   k_probeself : v10 mirror probing (62 probes -> both hit directions)
//                 -- measured ~212 us non-GEMM total
// ---------------------------------------------------------------------------

#define GRIDL 192
#define NVOX  (192*192*192)
#define NTAP  125
#define CTAP  62
#define NSEQ  124
#define RCAP  8192
#define TM    128
#define GT    320
#define NCTA  296
#define MAXT  50
#define NTK   (NSEQ*MAXT)
#define FST2  140              // fsT row stride (floats), skewed layout

__device__ float g_Wc[2304];
__device__ float g_Kdup[(size_t)NSEQ * 12800];
__device__ int   g_vol[NVOX];
__device__ int   g_tcnt[NSEQ];
__device__ int2  g_hits[(size_t)NSEQ * RCAP];

// ---- asm helpers -----------------------------------------------------------
__device__ __forceinline__ void cp16(void* dst, const void* src) {
    unsigned d = (unsigned)__cvta_generic_to_shared(dst);
    asm volatile("cp.async.cg.shared.global [%0], [%1], 16;\n" :: "r"(d), "l"(src));
}
__device__ __forceinline__ void cp_commit() { asm volatile("cp.async.commit_group;\n"); }
__device__ __forceinline__ void cp_wait0() { asm volatile("cp.async.wait_group 0;\n" ::: "memory"); }
__device__ __forceinline__ void ffma2(unsigned long long& d, unsigned long long a,
                                      unsigned long long b) {
    asm volatile("fma.rn.f32x2 %0, %1, %2, %0;" : "+l"(d) : "l"(a), "l"(b));
}
__device__ __forceinline__ void red4(float* p, float a, float b, float c, float d) {
    asm volatile("red.global.add.v4.f32 [%0], {%1,%2,%3,%4};"
                 :: "l"(p), "f"(a), "f"(b), "f"(c), "f"(d) : "memory");
}
__device__ __forceinline__ float lo32(unsigned long long v) {
    return __uint_as_float((unsigned)v);
}
__device__ __forceinline__ float hi32(unsigned long long v) {
    return __uint_as_float((unsigned)(v >> 32));
}

// ---- k_prep ----------------------------------------------------------------
__global__ void k_prep(const float* __restrict__ weight) {
    __shared__ float e[8];
    __shared__ float sW[2304];
    const int p = blockIdx.x;
    const int tid = threadIdx.x;

    float dx = (float)(p / 25) - 2.f;
    float dy = (float)((p / 5) % 5) - 2.f;
    float dz = (float)(p % 5) - 2.f;
    if (tid < 8) {
        float d = sqrtf(dx * dx + dy * dy + dz * dz);
        const float step = 2.5f / 9.f;
        float c = step * (float)(tid + 1);
        float t = (d - c) / step;
        float ev = 0.f;
        if (fabsf(t) < 1.f) {
            float s = 1.f - t * t;
            ev = 1.14136f * expf(2.f) * expf(-2.f / s);
        }
        e[tid] = ev;
    }
    __syncthreads();

    const float ALPHA = 0.14433756729740643f;   // 1/sqrt(48)
    const float INV125 = 1.f / 125.f;
    const float INVS3 = 0.5773502691896258f;    // 1/sqrt(3)
    for (int c = tid; c < 2304; c += blockDim.x) {
        float s = 0.f;
        #pragma unroll
        for (int r = 0; r < 8; r++) s += e[r] * weight[r * 2304 + c];
        s *= INV125;
        float sc = (c < 1792) ? ALPHA : ALPHA * INVS3;
        s *= sc;
        sW[c] = s;
        if (p == CTAP) g_Wc[c] = s;
    }
    __syncthreads();

    if (p == CTAP) return;
    const int seq = p - (p > CTAP);
    float d2 = dx * dx + dy * dy + dz * dz;
    float inv = 1.7320508075688772f / sqrtf(d2);
    float v[3] = {dx * inv, dy * inv, dz * inv};
    float* D = g_Kdup + (size_t)seq * 12800;
    for (int idx = tid; idx < 6400; idx += blockDim.x) {
        int j = idx / 80, c = idx % 80;
        float val;
        if (j < 32) {
            if (c < 32) val = sW[j * 32 + c];
            else { int cc = c - 32; val = sW[1024 + j * 16 + cc / 3] * v[cc % 3]; }
        } else {
            int jj = j - 32; int i = jj / 3, m = jj % 3;
            if (c < 32) val = sW[1792 + i * 32 + c] * v[m];
            else { int cc = c - 32;
                   val = (m == cc % 3) ? sW[1536 + i * 16 + cc / 3] : 0.f; }
        }
        D[j * 160 + 2 * c] = val;
        D[j * 160 + 2 * c + 1] = val;
    }
}

// ---- k_scatter -------------------------------------------------------------
__global__ void k_scatter(const int* __restrict__ coords, int n) {
    int i = blockIdx.x * blockDim.x + threadIdx.x;
    if (i < NSEQ) g_tcnt[i] = 0;
    if (i < n) {
        int x = coords[3 * i], y = coords[3 * i + 1], z = coords[3 * i + 2];
        g_vol[(x * GRIDL + y) * GRIDL + z] = i + 1;
    }
}

// ---- k_probeself: self+center + mirror probing -----------------------------
__global__ void k_probeself(const float* __restrict__ feats,
                            const float* __restrict__ wsc0,
                            const float* __restrict__ wsc1,
                            const int* __restrict__ coords,
                            float* __restrict__ out, int n)
{
    __shared__ float w0s[1024];
    __shared__ float w1s[256];
    __shared__ int bcnt[NSEQ];
    __shared__ int gbase[NSEQ];
    const int tid = threadIdx.x;

    if (tid < NSEQ) bcnt[tid] = 0;
    for (int i = tid; i < 1024; i += 256)
        w0s[i] = wsc0[i] * 0.17677669529663687f + g_Wc[i];
    if (tid < 256)
        w1s[tid] = wsc1[tid] * 0.25f + g_Wc[1536 + tid];
    __syncthreads();

    const int pt = blockIdx.x * 256 + tid;
    const bool valid = (pt < n);
    int cx = 0, cy = 0, cz = 0;
    unsigned m[2] = {0u, 0u};    // probe taps 0..61 only (mirror pairs)

    if (valid) {
        cx = coords[3 * pt]; cy = coords[3 * pt + 1]; cz = coords[3 * pt + 2];

        // self + center term (direct store)
        const float* f = feats + (size_t)pt * 80;
        float* o = out + (size_t)pt * 80;
        float fr[48];
        #pragma unroll
        for (int i = 0; i < 32; i++) fr[i] = f[i];
        #pragma unroll
        for (int c = 0; c < 32; c++) {
            float s = 0.f;
            #pragma unroll
            for (int i = 0; i < 32; i++) s += fr[i] * w0s[i * 32 + c];
            o[c] = s;
        }
        #pragma unroll
        for (int i = 0; i < 48; i++) fr[i] = f[32 + i];
        #pragma unroll
        for (int k = 0; k < 16; k++) {
            float s0 = 0.f, s1 = 0.f, s2 = 0.f;
            #pragma unroll
            for (int i = 0; i < 16; i++) {
                float w = w1s[i * 16 + k];
                s0 += fr[i * 3 + 0] * w;
                s1 += fr[i * 3 + 1] * w;
                s2 += fr[i * 3 + 2] * w;
            }
            o[32 + k * 3 + 0] = s0;
            o[32 + k * 3 + 1] = s1;
            o[32 + k * 3 + 2] = s2;
        }

        // pass A: probe taps 0..61; each hit implies both directions
        #pragma unroll
        for (int w = 0; w < 2; w++) {
            unsigned mw = 0u;
            #pragma unroll 4
            for (int j = 0; j < 32; j++) {
                int p = w * 32 + j;
                if (p < CTAP) {
                    int x = cx + p / 25 - 2, y = cy + (p / 5) % 5 - 2, z = cz + p % 5 - 2;
                    if ((unsigned)x < (unsigned)GRIDL && (unsigned)y < (unsigned)GRIDL &&
                        (unsigned)z < (unsigned)GRIDL) {
                        if (__ldg(&g_vol[(x * GRIDL + y) * GRIDL + z]) > 0) {
                            mw |= (1u << j);
                            atomicAdd(&bcnt[p], 1);
                            atomicAdd(&bcnt[123 - p], 1);
                        }
                    }
                }
            }
            m[w] = mw;
        }
    }
    __syncthreads();

    if (tid < NSEQ) {
        int c = bcnt[tid];
        gbase[tid] = c ? (tid * RCAP + atomicAdd(&g_tcnt[tid], c)) : 0;
        bcnt[tid] = 0;
    }
    __syncthreads();

    // pass B: re-probe hits; write forward + mirrored records
    if (valid) {
        #pragma unroll
        for (int w = 0; w < 2; w++) {
            unsigned mw = m[w];
            while (mw) {
                int j = __ffs(mw) - 1; mw &= mw - 1;
                int p = w * 32 + j;
                int x = cx + p / 25 - 2, y = cy + (p / 5) % 5 - 2, z = cz + p % 5 - 2;
                int nb = g_vol[(x * GRIDL + y) * GRIDL + z] - 1;
                int sf = p, sb = 123 - p;
                int slotf = gbase[sf] + atomicAdd(&bcnt[sf], 1);
                if (slotf < (sf + 1) * RCAP) g_hits[slotf] = make_int2(nb, pt);
                int slotb = gbase[sb] + atomicAdd(&bcnt[sb], 1);
                if (slotb < (sb + 1) * RCAP) g_hits[slotb] = make_int2(pt, nb);
            }
        }
    }
}

// ---- k_gemm: exact v9 config (GT=320, 8h x 4c, skewed fsT) -----------------
__global__ void __launch_bounds__(GT, 2)
k_gemm(const float* __restrict__ feats, float* __restrict__ out)
{
    extern __shared__ float smg[];
    float* fsT  = smg;               // [80][FST2] skewed transposed feats
    float* wdup = smg + 80 * FST2;   // [80][160] duplicated weights

    const int tid = threadIdx.x;
    const int wp = tid >> 5, lane = tid & 31;
    const int cc = 2 * wp + (lane >> 4);        // 0..19 channel group
    const int hg = lane & 15;                   // 0..15 hit group
    const int hb = hg * 8;
    const int aoff = hg * 8 + (hg >> 2) * 4;    // skewed fsT float offset

    const int t0 = (int)((long long)blockIdx.x * NTK / NCTA);
    const int t1 = (int)((long long)(blockIdx.x + 1) * NTK / NCTA);
    int cur_seq = -1;

    for (int t = t0; t < t1; t++) {
        const int seq = t / MAXT, lt = t - seq * MAXT;
        int cnt = g_tcnt[seq];
        if (cnt > MAXT * TM) cnt = MAXT * TM;
        if (lt * TM >= cnt) continue;
        const int base = seq * RCAP + lt * TM;
        int cnt_t = cnt - lt * TM;
        if (cnt_t > TM) cnt_t = TM;

        __syncthreads();   // previous tile's smem readers done

        const bool neww = (seq != cur_seq);
        if (neww) {
            cur_seq = seq;
            const float4* ws = (const float4*)(g_Kdup + (size_t)seq * 12800);
            float4* wd = (float4*)wdup;
            #pragma unroll
            for (int k = 0; k < 10; k++) cp16(wd + tid + k * GT, ws + tid + k * GT);
            cp_commit();
        }
        // gather feats -> skewed transpose (conflict-free STS)
        #pragma unroll
        for (int i = 0; i < 8; i++) {
            int idx = tid + i * GT;
            int kq = idx >> 7, h = idx & 127;
            int hh = (h < cnt_t) ? h : cnt_t - 1;
            int src = g_hits[base + hh].x;
            float4 f = __ldg((const float4*)(feats + (size_t)src * 80) + kq);
            int hg2 = h >> 3, j = h & 7;
            int foff = hg2 * 8 + (hg2 >> 2) * 4 + j;
            int kb = kq * 4;
            fsT[(kb + 0) * FST2 + foff] = f.x;
            fsT[(kb + 1) * FST2 + foff] = f.y;
            fsT[(kb + 2) * FST2 + foff] = f.z;
            fsT[(kb + 3) * FST2 + foff] = f.w;
        }
        if (neww) cp_wait0();
        __syncthreads();

        unsigned long long acc[4][4];
        #pragma unroll
        for (int a = 0; a < 4; a++)
            #pragma unroll
            for (int b = 0; b < 4; b++) acc[a][b] = 0ull;

        #pragma unroll 4
        for (int k = 0; k < 80; k++) {
            const ulonglong2* fa = (const ulonglong2*)(fsT + k * FST2 + aoff);
            ulonglong2 A0 = fa[0], A1 = fa[1];
            const ulonglong2* wb = (const ulonglong2*)(wdup + k * 160 + cc * 8);
            ulonglong2 B0 = wb[0], B1 = wb[1];
            ffma2(acc[0][0], A0.x, B0.x); ffma2(acc[0][1], A0.x, B0.y);
            ffma2(acc[0][2], A0.x, B1.x); ffma2(acc[0][3], A0.x, B1.y);
            ffma2(acc[1][0], A0.y, B0.x); ffma2(acc[1][1], A0.y, B0.y);
            ffma2(acc[1][2], A0.y, B1.x); ffma2(acc[1][3], A0.y, B1.y);
            ffma2(acc[2][0], A1.x, B0.x); ffma2(acc[2][1], A1.x, B0.y);
            ffma2(acc[2][2], A1.x, B1.x); ffma2(acc[2][3], A1.x, B1.y);
            ffma2(acc[3][0], A1.y, B0.x); ffma2(acc[3][1], A1.y, B0.y);
            ffma2(acc[3][2], A1.y, B1.x); ffma2(acc[3][3], A1.y, B1.y);
        }

        #pragma unroll
        for (int pr = 0; pr < 4; pr++) {
            int h0 = hb + pr * 2;
            if (h0 < cnt_t) {
                int dst = g_hits[base + h0].y;
                red4(out + (size_t)dst * 80 + cc * 4,
                     lo32(acc[pr][0]), lo32(acc[pr][1]),
                     lo32(acc[pr][2]), lo32(acc[pr][3]));
            }
            if (h0 + 1 < cnt_t) {
                int dst = g_hits[base + h0 + 1].y;
                red4(out + (size_t)dst * 80 + cc * 4,
                     hi32(acc[pr][0]), hi32(acc[pr][1]),
                     hi32(acc[pr][2]), hi32(acc[pr][3]));
            }
        }
    }
}

// ---------------------------------------------------------------------------
extern "C" void kernel_launch(void* const* d_in, const int* in_sizes, int n_in,
                              void* d_out, int out_size) {
    const float* feats  = (const float*)d_in[0];
    const float* weight = (const float*)d_in[1];
    const float* wsc0   = (const float*)d_in[2];
    const float* wsc1   = (const float*)d_in[3];
    const int*   coords = (const int*)d_in[4];
    float* out = (float*)d_out;
    int n = in_sizes[0] / 80;

    const int SMG = (80 * FST2 + 80 * 160) * 4;
    cudaFuncSetAttribute(k_gemm, cudaFuncAttributeMaxDynamicSharedMemorySize, SMG);

    int nblk = (n + 255) / 256;
    k_prep<<<NTAP, 256>>>(weight);
    k_scatter<<<nblk, 256>>>(coords, n);
    k_probeself<<<nblk, 256>>>(feats, wsc0, wsc1, coords, out, n);
    k_gemm<<<NCTA, GT, SMG>>>(feats, out);
}